// round 15
// baseline (speedup 1.0000x reference)
#include <cuda_runtime.h>
#include <cuda_fp16.h>
#include <cstdint>

// Dice loss: pred (8,62,512,512) f32 logits, target (8,512,512) i32 -> scalar f32.
// Single HBM pass (520MB), single launch.
// R14 vs R13 (107us; MUFU ~108K cyc/SMSP was the hidden binder):
//  - exp computed with ex2.approx.f16x2: 62 MUFU per pair-iter instead of 124
//  - denominator accumulated in half2 (HADD2) instead of 124 f32 FADDs
//  - et via SEL-chain over packed e (restores exact DRAM byte count; R13 leaked ~42MB
//    through the et reload + __ldcs interplay)
//  - keep: 2 px/thread float2 loads, class-paired half2 e + acc, 304x256, 16 warps/SM

#define NC      62
#define NCH     31             // class pairs
#define HWV     (512 * 512)
#define NPIX    (8 * 512 * 512)
#define NQ      (NPIX / 2)
#define IGNORE  255
#define NBLK    304            // 2 CTAs/SM x 152 SMs
#define NW      8              // warps per CTA
#define KP      512.0f
#define KPINV   (1.0f / 512.0f)

__device__ float g_pred_part[NC * NBLK];   // [c][b] per-CTA sum of softmax probs
__device__ float g_ic_part[NC * NBLK];     // [c][b] packed: KP*count + inter
__device__ unsigned g_ticket;              // zero-init; last CTA resets to 0

__device__ __forceinline__ __half2 ex2_h2(__half2 a) {
    __half2 r;
    asm("ex2.approx.f16x2 %0, %1;"
        : "=r"(*(uint32_t*)&r) : "r"(*(const uint32_t*)&a));
    return r;
}

__global__ __launch_bounds__(256, 2)
void dice_main(const float* __restrict__ pred, const int* __restrict__ target,
               float* __restrict__ out) {
    __shared__ float s_ic[NC];             // packed inter+count, per class
    __shared__ float s1[NW][NC];           // per-warp staging for final reduction
    __shared__ float sh_ds[NC];
    __shared__ float sh_nv[NC];
    __shared__ bool  s_last;

    const int tid = threadIdx.x;
    for (int i = tid; i < NC; i += 256) s_ic[i] = 0.f;
    __syncthreads();

    const __half2 h2z = __float2half2_rn(0.f);
    __half2 acc_h[NCH];        // packed {class 2j, class 2j+1} prob sums (fp16)
#pragma unroll
    for (int j = 0; j < NCH; ++j) acc_h[j] = h2z;

    const float L2E = 1.4426950408889634f;
    const int stride = gridDim.x * blockDim.x;

    for (int q = blockIdx.x * blockDim.x + tid; q < NQ; q += stride) {
        const int p  = q << 1;               // first pixel of the pair
        const int n  = p >> 18;
        const int hw = p & (HWV - 1);        // even -> float2 aligned
        const float* base = pred + (size_t)n * (NC * HWV) + hw;

        const int2 tt = *(const int2*)(target + p);
        const bool v0 = (tt.x != IGNORE);
        const bool v1 = (tt.y != IGNORE);
        const int  j0 = (v0 ? tt.x : -2) >> 1;  // class-pair index of target
        const int  j1 = (v1 ? tt.y : -2) >> 1;
        const int  o0 = tt.x & 1;               // half within the pair
        const int  o1 = tt.y & 1;

        __half2 epk0[NCH];     // pixel0: {e[2j], e[2j+1]}
        __half2 epk1[NCH];     // pixel1: {e[2j], e[2j+1]}
        __half2 dA0 = h2z, dB0 = h2z, dA1 = h2z, dB1 = h2z;   // denom partials

#pragma unroll
        for (int j = 0; j < NCH; ++j) {
            const int c = j << 1;
            const float2 xa = __ldcs((const float2*)(base + (size_t)c * HWV));       // class c,   pix 0/1
            const float2 xb = __ldcs((const float2*)(base + (size_t)(c + 1) * HWV)); // class c+1, pix 0/1
            // pack log2-scaled args per pixel, one vector ex2 per pixel per pair
            const __half2 e0 = ex2_h2(__floats2half2_rn(xa.x * L2E, xb.x * L2E));
            const __half2 e1 = ex2_h2(__floats2half2_rn(xa.y * L2E, xb.y * L2E));
            epk0[j] = e0;
            epk1[j] = e1;
            if (j & 1) { dB0 = __hadd2(dB0, e0); dB1 = __hadd2(dB1, e1); }
            else       { dA0 = __hadd2(dA0, e0); dA1 = __hadd2(dA1, e1); }
        }

        const __half2 s0 = __hadd2(dA0, dB0);
        const __half2 s1h = __hadd2(dA1, dB1);
        const float d0 = __low2float(s0) + __high2float(s0);
        const float d1 = __low2float(s1h) + __high2float(s1h);

        float inv0, inv1;
        asm("rcp.approx.ftz.f32 %0, %1;" : "=f"(inv0) : "f"(d0));
        asm("rcp.approx.ftz.f32 %0, %1;" : "=f"(inv1) : "f"(d1));
        const float i0 = v0 ? inv0 : 0.f;
        const float i1 = v1 ? inv1 : 0.f;

        // extract e at target class via SEL chain over the packed arrays
        __half2 sel0 = h2z, sel1 = h2z;
#pragma unroll
        for (int j = 0; j < NCH; ++j) {
            sel0 = (j == j0) ? epk0[j] : sel0;
            sel1 = (j == j1) ? epk1[j] : sel1;
        }
        const float et0 = o0 ? __high2float(sel0) : __low2float(sel0);
        const float et1 = o1 ? __high2float(sel1) : __low2float(sel1);
        if (v0) atomicAdd(&s_ic[tt.x], fmaf(et0, inv0, KP));
        if (v1) atomicAdd(&s_ic[tt.y], fmaf(et1, inv1, KP));

        const __half2 hi0 = __float2half2_rn(i0);
        const __half2 hi1 = __float2half2_rn(i1);
#pragma unroll
        for (int j = 0; j < NCH; ++j)
            acc_h[j] = __hfma2(epk0[j], hi0, __hfma2(epk1[j], hi1, acc_h[j]));
    }

    // Flush fp16 accumulators to fp32 (only live after the main loop).
    float acc1[NC];
#pragma unroll
    for (int j = 0; j < NCH; ++j) {
        const float2 f = __half22float2(acc_h[j]);
        acc1[2 * j]     = f.x;
        acc1[2 * j + 1] = f.y;
    }

    // Reduce acc1: warp butterfly per class -> shared -> per-CTA global slot.
    const int lane = tid & 31;
    const int w    = tid >> 5;
#pragma unroll
    for (int c = 0; c < NC; ++c) {
        float v = acc1[c];
#pragma unroll
        for (int s = 16; s; s >>= 1) v += __shfl_xor_sync(0xffffffffu, v, s);
        if (lane == 0) s1[w][c] = v;
    }
    __syncthreads();

    for (int c = tid; c < NC; c += 256) {
        float a = 0.f;
#pragma unroll
        for (int ww = 0; ww < NW; ++ww) a += s1[ww][c];
        g_pred_part[c * NBLK + blockIdx.x] = a;
        g_ic_part[c * NBLK + blockIdx.x]   = s_ic[c];
    }

    // ---- threadfence reduction: last CTA does the final reduce ----
    __threadfence();
    if (tid == 0) {
        const unsigned tk = atomicAdd(&g_ticket, 1u);
        s_last = (tk == NBLK - 1);
    }
    __syncthreads();
    if (!s_last) return;

    __threadfence();  // acquire: all CTAs' partials visible

    // 8 warps; warp w handles classes c = w, w+8, ... (L2-resident reads)
    for (int c = w; c < NC; c += NW) {
        float sp = 0.f, si = 0.f, sc = 0.f;
#pragma unroll
        for (int b = lane; b < NBLK; b += 32) {
            sp += g_pred_part[c * NBLK + b];
            const float v  = g_ic_part[c * NBLK + b];
            const float cf = floorf(v * KPINV);
            si = fmaf(-KP, cf, v) + si;   // inter part
            sc += cf;                      // count part
        }
#pragma unroll
        for (int s = 16; s; s >>= 1) {
            sp += __shfl_xor_sync(0xffffffffu, sp, s);
            si += __shfl_xor_sync(0xffffffffu, si, s);
            sc += __shfl_xor_sync(0xffffffffu, sc, s);
        }
        if (lane == 0) {
            const float u    = sp + sc;
            const float dice = (2.f * si + 1e-6f) / (u + 1e-6f);
            sh_ds[c] = (u > 0.f) ? dice : 0.f;
            sh_nv[c] = (u > 0.f) ? 1.f : 0.f;
        }
    }
    __syncthreads();
    if (tid == 0) {
        float ds = 0.f, nv = 0.f;
#pragma unroll
        for (int k = 0; k < NC; ++k) { ds += sh_ds[k]; nv += sh_nv[k]; }
        const float md = (nv > 0.f) ? (ds / fmaxf(nv, 1.f)) : 1.f;
        out[0] = 1.f - md;
        g_ticket = 0;   // reset for next graph replay
    }
}

extern "C" void kernel_launch(void* const* d_in, const int* in_sizes, int n_in,
                              void* d_out, int out_size) {
    const float* pred   = (const float*)d_in[0];
    const int*   target = (const int*)d_in[1];
    float*       out    = (float*)d_out;

    dice_main<<<NBLK, 256>>>(pred, target, out);
}

// round 16
// speedup vs baseline: 1.4842x; 1.4842x over previous
#include <cuda_runtime.h>
#include <cuda_fp16.h>
#include <cstdint>

// Dice loss: pred (8,62,512,512) f32 logits, target (8,512,512) i32 -> scalar f32.
// Single HBM pass (520MB), single launch.
// R15 = R9 skeleton (1 px/thread, LDG.32, 304x256, 16 warps/SM -> best WALL so far)
//       + f16x2 compute diet with guaranteed register headroom:
//  - per class pair: F2FP pack -> ex2.approx.f16x2 -> HADD2 denom -> HFMA2 acc
//    (~6 instr/pair vs R9's ~11; MUFU halved; no bf16 unpack LOPs)
//  - epk[31] + acc_h[31] half2 arrays = 62 regs -> ~95 total, NO spills (R14's bug)
//  - et via pre-burst __ldg reload of x[t] (leak-free per R11 audit), not SEL chain
//  - packed K=512 shared atomic for inter+count; fused last-CTA finish

#define NC      62
#define NCH     31             // class pairs
#define HWV     (512 * 512)
#define NPIX    (8 * 512 * 512)
#define IGNORE  255
#define NBLK    304            // 2 CTAs/SM x 152 SMs
#define NW      8              // warps per CTA
#define KP      512.0f
#define KPINV   (1.0f / 512.0f)

__device__ float g_pred_part[NC * NBLK];   // [c][b] per-CTA sum of softmax probs
__device__ float g_ic_part[NC * NBLK];     // [c][b] packed: KP*count + inter
__device__ unsigned g_ticket;              // zero-init; last CTA resets to 0

__device__ __forceinline__ __half2 ex2_h2(__half2 a) {
    __half2 r;
    asm("ex2.approx.f16x2 %0, %1;"
        : "=r"(*(uint32_t*)&r) : "r"(*(const uint32_t*)&a));
    return r;
}

__global__ __launch_bounds__(256, 2)
void dice_main(const float* __restrict__ pred, const int* __restrict__ target,
               float* __restrict__ out) {
    __shared__ float s_ic[NC];             // packed inter+count, per class
    __shared__ float s1[NW][NC];           // per-warp staging for final reduction
    __shared__ float sh_ds[NC];
    __shared__ float sh_nv[NC];
    __shared__ bool  s_last;

    const int tid = threadIdx.x;
    for (int i = tid; i < NC; i += 256) s_ic[i] = 0.f;
    __syncthreads();

    const __half2 h2z = __float2half2_rn(0.f);
    __half2 acc_h[NCH];        // {class 2j, class 2j+1} prob sums (fp16)
#pragma unroll
    for (int j = 0; j < NCH; ++j) acc_h[j] = h2z;

    const float L2E = 1.4426950408889634f;
    const int stride = gridDim.x * blockDim.x;

    for (int p = blockIdx.x * blockDim.x + tid; p < NPIX; p += stride) {
        const int n  = p >> 18;
        const int hw = p & (HWV - 1);
        const float* base = pred + (size_t)n * (NC * HWV) + hw;

        const int t = __ldg(target + p);
        const bool valid = (t != IGNORE);
        const int  ts = valid ? t : 0;

        // logit at target class, fetched before the streaming burst (L2/L1 hit later)
        const float xt = __ldg(base + (size_t)ts * HWV);

        __half2 epk[NCH];      // e^(x) per class pair (fp16)
        __half2 dh0 = h2z, dh1 = h2z;

#pragma unroll
        for (int j = 0; j < NCH; ++j) {
            const int c = j << 1;
            const float xa = __ldcs(base + (size_t)c * HWV);
            const float xb = __ldcs(base + (size_t)(c + 1) * HWV);
            const __half2 e = ex2_h2(__floats2half2_rn(xa * L2E, xb * L2E));
            epk[j] = e;
            if (j & 1) dh1 = __hadd2(dh1, e);
            else       dh0 = __hadd2(dh0, e);
        }

        const __half2 dh = __hadd2(dh0, dh1);
        const float d = __low2float(dh) + __high2float(dh);

        float inv;
        asm("rcp.approx.ftz.f32 %0, %1;" : "=f"(inv) : "f"(d));
        const float invv = valid ? inv : 0.f;

        // prob at target + packed count: one shared atomic per valid pixel
        float et;
        asm("ex2.approx.ftz.f32 %0, %1;" : "=f"(et) : "f"(xt * L2E));
        if (valid) atomicAdd(&s_ic[t], fmaf(et, inv, KP));

        const __half2 hinv = __float2half2_rn(invv);
#pragma unroll
        for (int j = 0; j < NCH; ++j)
            acc_h[j] = __hfma2(epk[j], hinv, acc_h[j]);
    }

    // Flush fp16 accumulators to fp32 (only live after the main loop).
    float acc1[NC];
#pragma unroll
    for (int j = 0; j < NCH; ++j) {
        const float2 f = __half22float2(acc_h[j]);
        acc1[2 * j]     = f.x;
        acc1[2 * j + 1] = f.y;
    }

    // Reduce acc1: warp butterfly per class -> shared -> per-CTA global slot.
    const int lane = tid & 31;
    const int w    = tid >> 5;
#pragma unroll
    for (int c = 0; c < NC; ++c) {
        float v = acc1[c];
#pragma unroll
        for (int s = 16; s; s >>= 1) v += __shfl_xor_sync(0xffffffffu, v, s);
        if (lane == 0) s1[w][c] = v;
    }
    __syncthreads();

    for (int c = tid; c < NC; c += 256) {
        float a = 0.f;
#pragma unroll
        for (int ww = 0; ww < NW; ++ww) a += s1[ww][c];
        g_pred_part[c * NBLK + blockIdx.x] = a;
        g_ic_part[c * NBLK + blockIdx.x]   = s_ic[c];
    }

    // ---- threadfence reduction: last CTA does the final reduce ----
    __threadfence();
    if (tid == 0) {
        const unsigned tk = atomicAdd(&g_ticket, 1u);
        s_last = (tk == NBLK - 1);
    }
    __syncthreads();
    if (!s_last) return;

    __threadfence();  // acquire: all CTAs' partials visible

    // 8 warps; warp w handles classes c = w, w+8, ... (L2-resident reads)
    for (int c = w; c < NC; c += NW) {
        float sp = 0.f, si = 0.f, sc = 0.f;
#pragma unroll
        for (int b = lane; b < NBLK; b += 32) {
            sp += g_pred_part[c * NBLK + b];
            const float v  = g_ic_part[c * NBLK + b];
            const float cf = floorf(v * KPINV);
            si = fmaf(-KP, cf, v) + si;   // inter part
            sc += cf;                      // count part
        }
#pragma unroll
        for (int s = 16; s; s >>= 1) {
            sp += __shfl_xor_sync(0xffffffffu, sp, s);
            si += __shfl_xor_sync(0xffffffffu, si, s);
            sc += __shfl_xor_sync(0xffffffffu, sc, s);
        }
        if (lane == 0) {
            const float u    = sp + sc;
            const float dice = (2.f * si + 1e-6f) / (u + 1e-6f);
            sh_ds[c] = (u > 0.f) ? dice : 0.f;
            sh_nv[c] = (u > 0.f) ? 1.f : 0.f;
        }
    }
    __syncthreads();
    if (tid == 0) {
        float ds = 0.f, nv = 0.f;
#pragma unroll
        for (int k = 0; k < NC; ++k) { ds += sh_ds[k]; nv += sh_nv[k]; }
        const float md = (nv > 0.f) ? (ds / fmaxf(nv, 1.f)) : 1.f;
        out[0] = 1.f - md;
        g_ticket = 0;   // reset for next graph replay
    }
}

extern "C" void kernel_launch(void* const* d_in, const int* in_sizes, int n_in,
                              void* d_out, int out_size) {
    const float* pred   = (const float*)d_in[0];
    const int*   target = (const int*)d_in[1];
    float*       out    = (float*)d_out;

    dice_main<<<NBLK, 256>>>(pred, target, out);
}

// round 17
// speedup vs baseline: 1.7232x; 1.1610x over previous
#include <cuda_runtime.h>
#include <cuda_fp16.h>
#include <cstdint>

// Dice loss: pred (8,62,512,512) f32 logits, target (8,512,512) i32 -> scalar f32.
// Single HBM pass (520MB), single launch.
// R16 = R15 (1 px/thread, f16x2 exp diet, 16 warps/SM)
//       + R9's in-loop SEL-chain for e[target]  (NO divergent x[t] reload:
//         that load was an up-to-32-line wavefront per warp and leaked ~42MB
//         DRAM via __ldcs evict-first re-fetches -> every post-R9 variant lost wall)
//  - per class pair: F2FP pack -> ex2.approx.f16x2 -> HADD2 denom -> HFMA2 acc
//  - et: 31 ISETP+SEL over the packed half2 e values (alu pipe is at 6.5%, cheap)
//  - packed K=512 shared atomic for inter+count; fused last-CTA finish

#define NC      62
#define NCH     31             // class pairs
#define HWV     (512 * 512)
#define NPIX    (8 * 512 * 512)
#define IGNORE  255
#define NBLK    304            // 2 CTAs/SM x 152 SMs
#define NW      8              // warps per CTA
#define KP      512.0f
#define KPINV   (1.0f / 512.0f)

__device__ float g_pred_part[NC * NBLK];   // [c][b] per-CTA sum of softmax probs
__device__ float g_ic_part[NC * NBLK];     // [c][b] packed: KP*count + inter
__device__ unsigned g_ticket;              // zero-init; last CTA resets to 0

__device__ __forceinline__ __half2 ex2_h2(__half2 a) {
    __half2 r;
    asm("ex2.approx.f16x2 %0, %1;"
        : "=r"(*(uint32_t*)&r) : "r"(*(const uint32_t*)&a));
    return r;
}

__global__ __launch_bounds__(256, 2)
void dice_main(const float* __restrict__ pred, const int* __restrict__ target,
               float* __restrict__ out) {
    __shared__ float s_ic[NC];             // packed inter+count, per class
    __shared__ float s1[NW][NC];           // per-warp staging for final reduction
    __shared__ float sh_ds[NC];
    __shared__ float sh_nv[NC];
    __shared__ bool  s_last;

    const int tid = threadIdx.x;
    for (int i = tid; i < NC; i += 256) s_ic[i] = 0.f;
    __syncthreads();

    const __half2 h2z = __float2half2_rn(0.f);
    __half2 acc_h[NCH];        // {class 2j, class 2j+1} prob sums (fp16)
#pragma unroll
    for (int j = 0; j < NCH; ++j) acc_h[j] = h2z;

    const float L2E = 1.4426950408889634f;
    const int stride = gridDim.x * blockDim.x;

    for (int p = blockIdx.x * blockDim.x + tid; p < NPIX; p += stride) {
        const int n  = p >> 18;
        const int hw = p & (HWV - 1);
        const float* base = pred + (size_t)n * (NC * HWV) + hw;

        const int t = __ldg(target + p);
        const bool valid = (t != IGNORE);
        const int  jt = valid ? (t >> 1) : -1;   // class-pair index of target
        const int  ot = t & 1;                    // half within the pair

        __half2 epk[NCH];      // e^(x) per class pair (fp16)
        __half2 sel = h2z;     // e at target's class pair
        __half2 dh0 = h2z, dh1 = h2z;

#pragma unroll
        for (int j = 0; j < NCH; ++j) {
            const int c = j << 1;
            const float xa = __ldcs(base + (size_t)c * HWV);
            const float xb = __ldcs(base + (size_t)(c + 1) * HWV);
            const __half2 e = ex2_h2(__floats2half2_rn(xa * L2E, xb * L2E));
            epk[j] = e;
            sel = (j == jt) ? e : sel;           // SEL-chain capture of e[target pair]
            if (j & 1) dh1 = __hadd2(dh1, e);
            else       dh0 = __hadd2(dh0, e);
        }

        const __half2 dh = __hadd2(dh0, dh1);
        const float d = __low2float(dh) + __high2float(dh);

        float inv;
        asm("rcp.approx.ftz.f32 %0, %1;" : "=f"(inv) : "f"(d));
        const float invv = valid ? inv : 0.f;

        // prob at target + packed count: one shared atomic per valid pixel
        const float et = ot ? __high2float(sel) : __low2float(sel);
        if (valid) atomicAdd(&s_ic[t], fmaf(et, inv, KP));

        const __half2 hinv = __float2half2_rn(invv);
#pragma unroll
        for (int j = 0; j < NCH; ++j)
            acc_h[j] = __hfma2(epk[j], hinv, acc_h[j]);
    }

    // Flush fp16 accumulators to fp32 (only live after the main loop).
    float acc1[NC];
#pragma unroll
    for (int j = 0; j < NCH; ++j) {
        const float2 f = __half22float2(acc_h[j]);
        acc1[2 * j]     = f.x;
        acc1[2 * j + 1] = f.y;
    }

    // Reduce acc1: warp butterfly per class -> shared -> per-CTA global slot.
    const int lane = tid & 31;
    const int w    = tid >> 5;
#pragma unroll
    for (int c = 0; c < NC; ++c) {
        float v = acc1[c];
#pragma unroll
        for (int s = 16; s; s >>= 1) v += __shfl_xor_sync(0xffffffffu, v, s);
        if (lane == 0) s1[w][c] = v;
    }
    __syncthreads();

    for (int c = tid; c < NC; c += 256) {
        float a = 0.f;
#pragma unroll
        for (int ww = 0; ww < NW; ++ww) a += s1[ww][c];
        g_pred_part[c * NBLK + blockIdx.x] = a;
        g_ic_part[c * NBLK + blockIdx.x]   = s_ic[c];
    }

    // ---- threadfence reduction: last CTA does the final reduce ----
    __threadfence();
    if (tid == 0) {
        const unsigned tk = atomicAdd(&g_ticket, 1u);
        s_last = (tk == NBLK - 1);
    }
    __syncthreads();
    if (!s_last) return;

    __threadfence();  // acquire: all CTAs' partials visible

    // 8 warps; warp w handles classes c = w, w+8, ... (L2-resident reads)
    for (int c = w; c < NC; c += NW) {
        float sp = 0.f, si = 0.f, sc = 0.f;
#pragma unroll
        for (int b = lane; b < NBLK; b += 32) {
            sp += g_pred_part[c * NBLK + b];
            const float v  = g_ic_part[c * NBLK + b];
            const float cf = floorf(v * KPINV);
            si = fmaf(-KP, cf, v) + si;   // inter part
            sc += cf;                      // count part
        }
#pragma unroll
        for (int s = 16; s; s >>= 1) {
            sp += __shfl_xor_sync(0xffffffffu, sp, s);
            si += __shfl_xor_sync(0xffffffffu, si, s);
            sc += __shfl_xor_sync(0xffffffffu, sc, s);
        }
        if (lane == 0) {
            const float u    = sp + sc;
            const float dice = (2.f * si + 1e-6f) / (u + 1e-6f);
            sh_ds[c] = (u > 0.f) ? dice : 0.f;
            sh_nv[c] = (u > 0.f) ? 1.f : 0.f;
        }
    }
    __syncthreads();
    if (tid == 0) {
        float ds = 0.f, nv = 0.f;
#pragma unroll
        for (int k = 0; k < NC; ++k) { ds += sh_ds[k]; nv += sh_nv[k]; }
        const float md = (nv > 0.f) ? (ds / fmaxf(nv, 1.f)) : 1.f;
        out[0] = 1.f - md;
        g_ticket = 0;   // reset for next graph replay
    }
}

extern "C" void kernel_launch(void* const* d_in, const int* in_sizes, int n_in,
                              void* d_out, int out_size) {
    const float* pred   = (const float*)d_in[0];
    const int*   target = (const int*)d_in[1];
    float*       out    = (float*)d_out;

    dice_main<<<NBLK, 256>>>(pred, target, out);
}